// round 6
// baseline (speedup 1.0000x reference)
#include <cuda_runtime.h>
#include <math.h>
#include <stdint.h>

#define LQ 2048
#define DD 1024
#define NH 16
#define DHD 64

__device__ float g_h [LQ*DD];
__device__ float g_q [NH*LQ*DHD];
__device__ float g_k [NH*LQ*DHD];
__device__ float g_v [NH*LQ*DHD];
__device__ float g_o [LQ*DD];
__device__ float g_yo[LQ*DD];
__device__ float g_gg[LQ*DD];

__device__ __forceinline__ uint32_t f2tf(float f) {
    uint32_t u;
    asm("cvt.rna.tf32.f32 %0, %1;" : "=r"(u) : "f"(f));
    return u;
}

__device__ __forceinline__ void mma8(float* c,
                                     uint32_t a0, uint32_t a1, uint32_t a2, uint32_t a3,
                                     uint32_t b0, uint32_t b1) {
    asm volatile("mma.sync.aligned.m16n8k8.row.col.f32.tf32.tf32.f32 "
        "{%0,%1,%2,%3}, {%4,%5,%6,%7}, {%8,%9}, {%0,%1,%2,%3};"
        : "+f"(c[0]), "+f"(c[1]), "+f"(c[2]), "+f"(c[3])
        : "r"(a0), "r"(a1), "r"(a2), "r"(a3), "r"(b0), "r"(b1));
}

#define POS(k) ((((k) & 3) * 2) + ((((k) >> 2) & 1)))

// ---------------- LayerNorm ----------------
__global__ void ln_kernel(const float* __restrict__ x,
                          const float* __restrict__ gamma,
                          const float* __restrict__ beta) {
    __shared__ float red[8];
    int row = blockIdx.x;
    int t = threadIdx.x;
    const float* xr = x + (size_t)row * DD;
    float v[4];
    float s = 0.f;
#pragma unroll
    for (int i = 0; i < 4; i++) { v[i] = xr[t + 256*i]; s += v[i]; }
#pragma unroll
    for (int o = 16; o; o >>= 1) s += __shfl_xor_sync(0xffffffffu, s, o);
    if ((t & 31) == 0) red[t >> 5] = s;
    __syncthreads();
    float tot = 0.f;
#pragma unroll
    for (int w = 0; w < 8; w++) tot += red[w];
    float mean = tot * (1.f / DD);
    __syncthreads();
    float s2 = 0.f;
#pragma unroll
    for (int i = 0; i < 4; i++) { float d = v[i] - mean; s2 += d*d; }
#pragma unroll
    for (int o = 16; o; o >>= 1) s2 += __shfl_xor_sync(0xffffffffu, s2, o);
    if ((t & 31) == 0) red[t >> 5] = s2;
    __syncthreads();
    float tot2 = 0.f;
#pragma unroll
    for (int w = 0; w < 8; w++) tot2 += red[w];
    float inv = rsqrtf(tot2 * (1.f / DD) + 1e-5f);
#pragma unroll
    for (int i = 0; i < 4; i++) {
        int c = t + 256*i;
        g_h[(size_t)row*DD + c] = (v[i] - mean) * inv * gamma[c] + beta[c];
    }
}

// ---------------- tf32 GEMM core (128x128, kc=16, double-buffered) ----------------
__device__ __forceinline__ void gemm_core(const float* __restrict__ A,
                                          const float* __restrict__ B,
                                          float* __restrict__ C, int mode,
                                          uint32_t* As, uint32_t* Bs) {
    // As/Bs: each 2 bufs x 2 ksteps x 1152 words
    int t = threadIdx.x;
    int bm = blockIdx.y * 128, bn = blockIdx.x * 128;
    int lane = t & 31, wid = t >> 5;
    int g = lane >> 2, tg = lane & 3;
    int wm = (wid >> 2) * 64, wn = (wid & 3) * 32;

    int am = t & 127, akq = (t >> 7) * 8;
    int bk = t & 15,  bnq = (t >> 4) * 8;
    int pb = POS(bk), ksb = bk >> 3;

    const float* Ap = A + (size_t)(bm + am) * 1024 + akq;
    const float* Bp = B + (size_t)bk * 1024 + bn + bnq;

    float acc[4][4][4];
#pragma unroll
    for (int i = 0; i < 4; i++)
#pragma unroll
        for (int j = 0; j < 4; j++)
#pragma unroll
            for (int q = 0; q < 4; q++) acc[i][j][q] = 0.f;

    float4 a1v = *(const float4*)(Ap);
    float4 a2v = *(const float4*)(Ap + 4);
    float4 b1v = *(const float4*)(Bp);
    float4 b2v = *(const float4*)(Bp + 4);

#define STORE_TILE(BUF)                                                          \
    {                                                                            \
        uint32_t* Ab = As + (BUF)*2304;                                          \
        uint32_t* Bb = Bs + (BUF)*2304;                                          \
        const float* aa = (const float*)&a1v;                                    \
        _Pragma("unroll")                                                        \
        for (int e = 0; e < 4; e++) {                                            \
            int kk = akq + e;                                                    \
            Ab[(kk >> 3)*1152 + am * 9 + POS(kk)] = f2tf(aa[e]);                 \
        }                                                                        \
        const float* ab = (const float*)&a2v;                                    \
        _Pragma("unroll")                                                        \
        for (int e = 0; e < 4; e++) {                                            \
            int kk = akq + 4 + e;                                                \
            Ab[(kk >> 3)*1152 + am * 9 + POS(kk)] = f2tf(ab[e]);                 \
        }                                                                        \
        const float* ba = (const float*)&b1v;                                    \
        _Pragma("unroll")                                                        \
        for (int e = 0; e < 4; e++)                                              \
            Bb[ksb*1152 + (bnq + e) * 9 + pb] = f2tf(ba[e]);                     \
        const float* bb = (const float*)&b2v;                                    \
        _Pragma("unroll")                                                        \
        for (int e = 0; e < 4; e++)                                              \
            Bb[ksb*1152 + (bnq + 4 + e) * 9 + pb] = f2tf(bb[e]);                 \
    }

#define COMPUTE(BUF)                                                             \
    {                                                                            \
        uint32_t* Ab = As + (BUF)*2304;                                          \
        uint32_t* Bb = Bs + (BUF)*2304;                                          \
        _Pragma("unroll")                                                        \
        for (int ks = 0; ks < 2; ks++) {                                         \
            uint32_t af[4][4];                                                   \
            uint32_t bf[4][2];                                                   \
            _Pragma("unroll")                                                    \
            for (int mt = 0; mt < 4; mt++) {                                     \
                const uint32_t* pa  = &Ab[ks*1152 + (wm + mt*16 + g)*9 + 2*tg];  \
                const uint32_t* pa2 = &Ab[ks*1152 + (wm + mt*16 + g + 8)*9 + 2*tg];\
                af[mt][0] = pa[0]; af[mt][1] = pa2[0];                           \
                af[mt][2] = pa[1]; af[mt][3] = pa2[1];                           \
            }                                                                    \
            _Pragma("unroll")                                                    \
            for (int nt = 0; nt < 4; nt++) {                                     \
                const uint32_t* pbp = &Bb[ks*1152 + (wn + nt*8 + g)*9 + 2*tg];   \
                bf[nt][0] = pbp[0]; bf[nt][1] = pbp[1];                          \
            }                                                                    \
            _Pragma("unroll")                                                    \
            for (int mt = 0; mt < 4; mt++)                                       \
                _Pragma("unroll")                                                \
                for (int nt = 0; nt < 4; nt++)                                   \
                    mma8(acc[mt][nt], af[mt][0], af[mt][1], af[mt][2], af[mt][3],\
                         bf[nt][0], bf[nt][1]);                                  \
        }                                                                        \
    }

    STORE_TILE(0);
    __syncthreads();
    int buf = 0;
    for (int k0 = 16; k0 < 1024; k0 += 16) {
        a1v = *(const float4*)(Ap + k0);
        a2v = *(const float4*)(Ap + k0 + 4);
        b1v = *(const float4*)(Bp + (size_t)k0 * 1024);
        b2v = *(const float4*)(Bp + (size_t)k0 * 1024 + 4);
        COMPUTE(buf);
        buf ^= 1;
        STORE_TILE(buf);
        __syncthreads();
    }
    COMPUTE(buf);

#pragma unroll
    for (int mt = 0; mt < 4; mt++) {
#pragma unroll
        for (int nt = 0; nt < 4; nt++) {
            int m = bm + wm + mt*16 + g;
            int n = bn + wn + nt*8 + 2*tg;
            float2 v0 = make_float2(acc[mt][nt][0], acc[mt][nt][1]);
            float2 v1 = make_float2(acc[mt][nt][2], acc[mt][nt][3]);
            if (mode == 0) {
                *(float2*)&C[(size_t)m*1024 + n] = v0;
                *(float2*)&C[(size_t)(m+8)*1024 + n] = v1;
            } else {
                size_t b0i = ((size_t)(n >> 6)*LQ + m)*DHD + (n & 63);
                size_t b1i = ((size_t)(n >> 6)*LQ + m + 8)*DHD + (n & 63);
                *(float2*)&C[b0i] = v0;
                *(float2*)&C[b1i] = v1;
            }
        }
    }
#undef STORE_TILE
#undef COMPUTE
}

// batched QKV: z selects weight/output (same A) -> head-major
__global__ void __launch_bounds__(256, 2)
gemm_qkv(const float* __restrict__ A,
         const float* __restrict__ Wq, const float* __restrict__ Wk,
         const float* __restrict__ Wv,
         float* __restrict__ Cq, float* __restrict__ Ck, float* __restrict__ Cv) {
    __shared__ uint32_t As[2*2*1152];
    __shared__ uint32_t Bs[2*2*1152];
    int z = blockIdx.z;
    const float* B = (z == 0) ? Wq : (z == 1) ? Wk : Wv;
    float* C = (z == 0) ? Cq : (z == 1) ? Ck : Cv;
    gemm_core(A, B, C, 1, As, Bs);
}

// batched Wo/Wg: z selects (A,B,C) pair, plain layout
__global__ void __launch_bounds__(256, 2)
gemm_ow(const float* __restrict__ Ao, const float* __restrict__ Wo,
        float* __restrict__ Co,
        const float* __restrict__ Ag, const float* __restrict__ Wg,
        float* __restrict__ Cg) {
    __shared__ uint32_t As[2*2*1152];
    __shared__ uint32_t Bs[2*2*1152];
    int z = blockIdx.z;
    const float* A = (z == 0) ? Ao : Ag;
    const float* B = (z == 0) ? Wo : Wg;
    float* C = (z == 0) ? Co : Cg;
    gemm_core(A, B, C, 0, As, Bs);
}

// ---------------- RoPE on q,k,v ----------------
__global__ void rope_kernel() {
    int idx = blockIdx.x * blockDim.x + threadIdx.x;   // NH*LQ*8
    int pair = idx & 7;
    int rest = idx >> 3;
    int l = rest & (LQ - 1);
    int base = rest * DHD;
    float invf = powf(10000.f, -(float)pair * 0.125f);
    float ang = (float)l * invf;
    float s, c;
    sincosf(ang, &s, &c);
    float a, b;
    a = g_q[base + pair]; b = g_q[base + pair + 8];
    g_q[base + pair] = a*c - b*s; g_q[base + pair + 8] = b*c + a*s;
    a = g_k[base + pair]; b = g_k[base + pair + 8];
    g_k[base + pair] = a*c - b*s; g_k[base + pair + 8] = b*c + a*s;
    a = g_v[base + pair]; b = g_v[base + pair + 8];
    g_v[base + pair] = a*c - b*s; g_v[base + pair + 8] = b*c + a*s;
}

// ---------------- fused attention: QK + online softmax stats + probs + AV ----------------
// CTA = (i-block of 128 rows, head). Two passes over j.
// smem word offsets:
//   Qs (pass1) / Ps (pass2):  0      .. 9216   (8 or 8 ksteps x 1152)
//   Ks (pass1) / Vs (pass2):  9216   .. 18432
//   mparts: 18432 (+512), sparts: 18944 (+512), Mrow: 19456 (+128), Sinv: 19584 (+128)
#define SMW_TOTAL 19712
__global__ void __launch_bounds__(256, 2)
attn_fused(const float* __restrict__ prev,
           float* __restrict__ dots, float* __restrict__ attn) {
    extern __shared__ uint32_t sm[];
    uint32_t* Qs = sm;
    uint32_t* Ks = sm + 9216;
    float* mparts = (float*)(sm + 18432);
    float* sparts = (float*)(sm + 18944);
    float* Mrow   = (float*)(sm + 19456);
    float* Sinv   = (float*)(sm + 19584);

    int t = threadIdx.x;
    int h = blockIdx.y;
    int i0 = ((int)gridDim.x - 1 - (int)blockIdx.x) * 128;   // heavy tiles first
    int lane = t & 31, wid = t >> 5;
    int g = lane >> 2, tg = lane & 3;
    int wm = (wid >> 2) * 64, wn = (wid & 3) * 32;

    const float* qh = g_q + (size_t)h*LQ*DHD;
    const float* kh = g_k + (size_t)h*LQ*DHD;
    const float* vh = g_v + (size_t)h*LQ*DHD;
    float slope = exp2f(-0.5f * (float)(h + 1));

    // ---- stage Q (128 x 64) ----
    {
        int m = t & 127, hk = (t >> 7) * 32;
        const float* qrow = qh + (size_t)(i0 + m)*DHD + hk;
#pragma unroll
        for (int q = 0; q < 8; q++) {
            float4 v = *(const float4*)(qrow + q*4);
            const float* vp = (const float*)&v;
#pragma unroll
            for (int e = 0; e < 4; e++) {
                int kk = hk + q*4 + e;
                Qs[(kk >> 3)*1152 + m*9 + POS(kk)] = f2tf(vp[e]);
            }
        }
    }

    float m_t[4][2], s_t[4][2];
#pragma unroll
    for (int i = 0; i < 4; i++)
#pragma unroll
        for (int r = 0; r < 2; r++) { m_t[i][r] = -3.4e38f; s_t[i][r] = 0.f; }

    // ================= PASS 1: dots + online stats =================
    for (int jc = 0; jc < LQ; jc += 128) {
        __syncthreads();
        // stage K chunk
        {
            int m = t & 127, hk = (t >> 7) * 32;
            const float* krow = kh + (size_t)(jc + m)*DHD + hk;
#pragma unroll
            for (int q = 0; q < 8; q++) {
                float4 w = *(const float4*)(krow + q*4);
                const float* wp = (const float*)&w;
#pragma unroll
                for (int e = 0; e < 4; e++) {
                    int kk = hk + q*4 + e;
                    Ks[(kk >> 3)*1152 + m*9 + POS(kk)] = f2tf(wp[e]);
                }
            }
        }
        __syncthreads();

        float acc[4][4][4];
#pragma unroll
        for (int i = 0; i < 4; i++)
#pragma unroll
            for (int j = 0; j < 4; j++)
#pragma unroll
                for (int q = 0; q < 4; q++) acc[i][j][q] = 0.f;

#pragma unroll
        for (int ks = 0; ks < 8; ks++) {
            uint32_t af[4][4];
            uint32_t bf[4][2];
#pragma unroll
            for (int mt = 0; mt < 4; mt++) {
                const uint32_t* pa  = &Qs[ks*1152 + (wm + mt*16 + g)*9 + 2*tg];
                const uint32_t* pa2 = &Qs[ks*1152 + (wm + mt*16 + g + 8)*9 + 2*tg];
                af[mt][0] = pa[0]; af[mt][1] = pa2[0];
                af[mt][2] = pa[1]; af[mt][3] = pa2[1];
            }
#pragma unroll
            for (int nt = 0; nt < 4; nt++) {
                const uint32_t* pbp = &Ks[ks*1152 + (wn + nt*8 + g)*9 + 2*tg];
                bf[nt][0] = pbp[0]; bf[nt][1] = pbp[1];
            }
#pragma unroll
            for (int mt = 0; mt < 4; mt++)
#pragma unroll
                for (int nt = 0; nt < 4; nt++)
                    mma8(acc[mt][nt], af[mt][0], af[mt][1], af[mt][2], af[mt][3],
                         bf[nt][0], bf[nt][1]);
        }

        // epilogue: bias, write dots, online stats per row
#pragma unroll
        for (int mt = 0; mt < 4; mt++) {
#pragma unroll
            for (int rr = 0; rr < 2; rr++) {
                int gi = i0 + wm + mt*16 + g + rr*8;
                size_t rowb = ((size_t)(h*LQ + gi))*LQ;
                float vals[8];
#pragma unroll
                for (int nt = 0; nt < 4; nt++) {
                    int j = jc + wn + nt*8 + 2*tg;
                    float2 pv = *(const float2*)&prev[rowb + j];
                    int rel0 = gi - j, rel1 = gi - (j + 1);
                    float2 ov;
                    ov.x = acc[mt][nt][rr*2+0]*0.125f + pv.x +
                           ((rel0 >= 0) ? (-slope*(float)rel0) : -1000000000.0f);
                    ov.y = acc[mt][nt][rr*2+1]*0.125f + pv.y +
                           ((rel1 >= 0) ? (-slope*(float)rel1) : -1000000000.0f);
                    *(float2*)&dots[rowb + j] = ov;
                    vals[nt*2]   = ov.x;
                    vals[nt*2+1] = ov.y;
                }
                float mloc = vals[0];
#pragma unroll
                for (int q = 1; q < 8; q++) mloc = fmaxf(mloc, vals[q]);
                float mold = m_t[mt][rr];
                float mnew = fmaxf(mold, mloc);
                float ssum = 0.f;
#pragma unroll
                for (int q = 0; q < 8; q++) ssum += __expf(vals[q] - mnew);
                s_t[mt][rr] = s_t[mt][rr] * __expf(mold - mnew) + ssum;
                m_t[mt][rr] = mnew;
            }
        }
    }

    // merge stats across quad (tg bits), then across the 4 n-warps via smem
#pragma unroll
    for (int mt = 0; mt < 4; mt++) {
#pragma unroll
        for (int rr = 0; rr < 2; rr++) {
            float m = m_t[mt][rr], s = s_t[mt][rr];
#pragma unroll
            for (int off = 1; off <= 2; off <<= 1) {
                float mo = __shfl_xor_sync(0xffffffffu, m, off);
                float so = __shfl_xor_sync(0xffffffffu, s, off);
                float mn = fmaxf(m, mo);
                s = s * __expf(m - mn) + so * __expf(mo - mn);
                m = mn;
            }
            if (tg == 0) {
                int lr = wm + mt*16 + g + rr*8;
                mparts[(wid & 3)*128 + lr] = m;
                sparts[(wid & 3)*128 + lr] = s;
            }
        }
    }
    __syncthreads();
    if (t < 128) {
        float m0 = mparts[t], m1 = mparts[128 + t];
        float m2 = mparts[256 + t], m3 = mparts[384 + t];
        float M = fmaxf(fmaxf(m0, m1), fmaxf(m2, m3));
        float S = sparts[t]       * __expf(m0 - M)
                + sparts[128 + t] * __expf(m1 - M)
                + sparts[256 + t] * __expf(m2 - M)
                + sparts[384 + t] * __expf(m3 - M);
        Mrow[t] = M;
        Sinv[t] = 1.f / S;
    }

    // ================= PASS 2: probs + attn write + AV =================
    uint32_t* Ps = Qs;          // alias (Q dead)
    uint32_t* Vs = Ks;          // alias
    int wm2 = wid * 16;
    float oacc[8][4];
#pragma unroll
    for (int i = 0; i < 8; i++)
#pragma unroll
        for (int q = 0; q < 4; q++) oacc[i][q] = 0.f;

    int jlive = i0 + 127;
    int prow = t >> 1, pc0 = (t & 1) * 32;
    int vj = t >> 2, vd0 = (t & 3) * 16;

    for (int jc = 0; jc < LQ; jc += 64) {
        int live = (jc <= jlive);
        __syncthreads();
        float M = Mrow[prow], Si = Sinv[prow];
        size_t rowb = ((size_t)(h*LQ + i0 + prow))*LQ + jc;
#pragma unroll
        for (int q = 0; q < 8; q++) {
            int c = pc0 + q*4;
            float4 dv = *(const float4*)&dots[rowb + c];
            float4 p;
            p.x = __expf(dv.x - M) * Si;
            p.y = __expf(dv.y - M) * Si;
            p.z = __expf(dv.z - M) * Si;
            p.w = __expf(dv.w - M) * Si;
            *(float4*)&attn[rowb + c] = p;
            if (live) {
                const float* pp = (const float*)&p;
#pragma unroll
                for (int e = 0; e < 4; e++) {
                    int cc = c + e;
                    Ps[(cc >> 3)*1152 + prow*9 + POS(cc & 7)] = f2tf(pp[e]);
                }
            }
        }
        if (live) {
            const float* vr = vh + (size_t)(jc + vj)*DHD + vd0;
#pragma unroll
            for (int q = 0; q < 4; q++) {
                float4 vv = *(const float4*)(vr + q*4);
                const float* wp = (const float*)&vv;
#pragma unroll
                for (int e = 0; e < 4; e++) {
                    int d = vd0 + q*4 + e;
                    Vs[(vj >> 3)*576 + d*9 + POS(vj & 7)] = f2tf(wp[e]);
                }
            }
            __syncthreads();
#pragma unroll
            for (int ks = 0; ks < 8; ks++) {
                const uint32_t* pa  = &Ps[ks*1152 + (wm2 + g)*9 + 2*tg];
                const uint32_t* pa2 = &Ps[ks*1152 + (wm2 + g + 8)*9 + 2*tg];
                uint32_t a0 = pa[0], a1 = pa2[0], a2 = pa[1], a3 = pa2[1];
#pragma unroll
                for (int nt = 0; nt < 8; nt++) {
                    const uint32_t* pbp = &Vs[ks*576 + (nt*8 + g)*9 + 2*tg];
                    mma8(oacc[nt], a0, a1, a2, a3, pbp[0], pbp[1]);
                }
            }
        }
    }

#pragma unroll
    for (int nt = 0; nt < 8; nt++) {
        int d = nt*8 + 2*tg;
        int i = i0 + wm2 + g;
        *(float2*)&g_o[(size_t)i*DD + h*DHD + d] =
            make_float2(oacc[nt][0], oacc[nt][1]);
        *(float2*)&g_o[(size_t)(i+8)*DD + h*DHD + d] =
            make_float2(oacc[nt][2], oacc[nt][3]);
    }
}

// ---------------- final: y = sigmoid(x@Wg+bg) * (o@Wo+bo) + x ----------------
__global__ void final_kernel(const float* __restrict__ x,
                             const float* __restrict__ bo,
                             const float* __restrict__ bg,
                             float* __restrict__ y) {
    int idx = blockIdx.x * 256 + threadIdx.x;
    int n = idx & (DD - 1);
    float yo = g_yo[idx] + bo[n];
    float gg = g_gg[idx] + bg[n];
    float gate = 1.f / (1.f + __expf(-gg));
    y[idx] = gate * yo + x[idx];
}

extern "C" void kernel_launch(void* const* d_in, const int* in_sizes, int n_in,
                              void* d_out, int out_size) {
    const float* x     = (const float*)d_in[0];
    const float* prev  = (const float*)d_in[1];
    const float* Wq    = (const float*)d_in[2];
    const float* Wk    = (const float*)d_in[3];
    const float* Wv    = (const float*)d_in[4];
    const float* Wo    = (const float*)d_in[5];
    const float* bo    = (const float*)d_in[6];
    const float* gamma = (const float*)d_in[7];
    const float* beta  = (const float*)d_in[8];
    const float* Wg    = (const float*)d_in[9];
    const float* bg    = (const float*)d_in[10];

    float* y    = (float*)d_out;
    float* attn = y + (size_t)LQ * DD;
    float* dots = attn + (size_t)NH * LQ * LQ;

    float *ph, *pq, *pk, *pv, *po, *pyo, *pgg;
    cudaGetSymbolAddress((void**)&ph,  g_h);
    cudaGetSymbolAddress((void**)&pq,  g_q);
    cudaGetSymbolAddress((void**)&pk,  g_k);
    cudaGetSymbolAddress((void**)&pv,  g_v);
    cudaGetSymbolAddress((void**)&po,  g_o);
    cudaGetSymbolAddress((void**)&pyo, g_yo);
    cudaGetSymbolAddress((void**)&pgg, g_gg);

    size_t asmb = (size_t)SMW_TOTAL * sizeof(uint32_t);
    cudaFuncSetAttribute(attn_fused, cudaFuncAttributeMaxDynamicSharedMemorySize, (int)asmb);

    ln_kernel<<<LQ, 256>>>(x, gamma, beta);

    gemm_qkv<<<dim3(8, 16, 3), 256>>>(ph, Wq, Wk, Wv, pq, pk, pv);

    rope_kernel<<<(NH*LQ*8)/256, 256>>>();

    attn_fused<<<dim3(16, 16), 256, asmb>>>(prev, dots, attn);

    gemm_ow<<<dim3(8, 16, 2), 256>>>(po, Wo, pyo, x, Wg, pgg);

    final_kernel<<<(LQ*DD)/256, 256>>>(x, bo, bg, y);
}

// round 8
// speedup vs baseline: 1.0200x; 1.0200x over previous
#include <cuda_runtime.h>
#include <math.h>
#include <stdint.h>

#define LQ 2048
#define DD 1024
#define NH 16
#define DHD 64

__device__ float g_h [LQ*DD];
__device__ float g_q [NH*LQ*DHD];
__device__ float g_k [NH*LQ*DHD];
__device__ float g_v [NH*LQ*DHD];
__device__ float g_o [LQ*DD];
__device__ float g_yo[LQ*DD];
__device__ float g_gg[LQ*DD];
__device__ float g_part[NH*LQ*16];
__device__ float g_sinv[NH*LQ];

__device__ __forceinline__ uint32_t f2tf(float f) {
    uint32_t u;
    asm("cvt.rna.tf32.f32 %0, %1;" : "=r"(u) : "f"(f));
    return u;
}

__device__ __forceinline__ void mma8(float* c,
                                     uint32_t a0, uint32_t a1, uint32_t a2, uint32_t a3,
                                     uint32_t b0, uint32_t b1) {
    asm volatile("mma.sync.aligned.m16n8k8.row.col.f32.tf32.tf32.f32 "
        "{%0,%1,%2,%3}, {%4,%5,%6,%7}, {%8,%9}, {%0,%1,%2,%3};"
        : "+f"(c[0]), "+f"(c[1]), "+f"(c[2]), "+f"(c[3])
        : "r"(a0), "r"(a1), "r"(a2), "r"(a3), "r"(b0), "r"(b1));
}

#define POS(k) ((((k) & 3) * 2) + ((((k) >> 2) & 1)))

// ---------------- LayerNorm ----------------
__global__ void ln_kernel(const float* __restrict__ x,
                          const float* __restrict__ gamma,
                          const float* __restrict__ beta) {
    __shared__ float red[8];
    int row = blockIdx.x;
    int t = threadIdx.x;
    const float* xr = x + (size_t)row * DD;
    float v[4];
    float s = 0.f;
#pragma unroll
    for (int i = 0; i < 4; i++) { v[i] = xr[t + 256*i]; s += v[i]; }
#pragma unroll
    for (int o = 16; o; o >>= 1) s += __shfl_xor_sync(0xffffffffu, s, o);
    if ((t & 31) == 0) red[t >> 5] = s;
    __syncthreads();
    float tot = 0.f;
#pragma unroll
    for (int w = 0; w < 8; w++) tot += red[w];
    float mean = tot * (1.f / DD);
    __syncthreads();
    float s2 = 0.f;
#pragma unroll
    for (int i = 0; i < 4; i++) { float d = v[i] - mean; s2 += d*d; }
#pragma unroll
    for (int o = 16; o; o >>= 1) s2 += __shfl_xor_sync(0xffffffffu, s2, o);
    if ((t & 31) == 0) red[t >> 5] = s2;
    __syncthreads();
    float tot2 = 0.f;
#pragma unroll
    for (int w = 0; w < 8; w++) tot2 += red[w];
    float inv = rsqrtf(tot2 * (1.f / DD) + 1e-5f);
#pragma unroll
    for (int i = 0; i < 4; i++) {
        int c = t + 256*i;
        g_h[(size_t)row*DD + c] = (v[i] - mean) * inv * gamma[c] + beta[c];
    }
}

// ---------------- tf32 GEMM core (128x128, kc=16, double-buffered) ----------------
__device__ __forceinline__ void gemm_core(const float* __restrict__ A,
                                          const float* __restrict__ B,
                                          float* __restrict__ C, int mode,
                                          uint32_t* As, uint32_t* Bs) {
    int t = threadIdx.x;
    int bm = blockIdx.y * 128, bn = blockIdx.x * 128;
    int lane = t & 31, wid = t >> 5;
    int g = lane >> 2, tg = lane & 3;
    int wm = (wid >> 2) * 64, wn = (wid & 3) * 32;

    int am = t & 127, akq = (t >> 7) * 8;
    int bk = t & 15,  bnq = (t >> 4) * 8;
    int pb = POS(bk), ksb = bk >> 3;

    const float* Ap = A + (size_t)(bm + am) * 1024 + akq;
    const float* Bp = B + (size_t)bk * 1024 + bn + bnq;

    float acc[4][4][4];
#pragma unroll
    for (int i = 0; i < 4; i++)
#pragma unroll
        for (int j = 0; j < 4; j++)
#pragma unroll
            for (int q = 0; q < 4; q++) acc[i][j][q] = 0.f;

    float4 a1v = *(const float4*)(Ap);
    float4 a2v = *(const float4*)(Ap + 4);
    float4 b1v = *(const float4*)(Bp);
    float4 b2v = *(const float4*)(Bp + 4);

#define STORE_TILE(BUF)                                                          \
    {                                                                            \
        uint32_t* Ab = As + (BUF)*2304;                                          \
        uint32_t* Bb = Bs + (BUF)*2304;                                          \
        const float* aa = (const float*)&a1v;                                    \
        _Pragma("unroll")                                                        \
        for (int e = 0; e < 4; e++) {                                            \
            int kk = akq + e;                                                    \
            Ab[(kk >> 3)*1152 + am * 9 + POS(kk)] = f2tf(aa[e]);                 \
        }                                                                        \
        const float* ab = (const float*)&a2v;                                    \
        _Pragma("unroll")                                                        \
        for (int e = 0; e < 4; e++) {                                            \
            int kk = akq + 4 + e;                                                \
            Ab[(kk >> 3)*1152 + am * 9 + POS(kk)] = f2tf(ab[e]);                 \
        }                                                                        \
        const float* ba = (const float*)&b1v;                                    \
        _Pragma("unroll")                                                        \
        for (int e = 0; e < 4; e++)                                              \
            Bb[ksb*1152 + (bnq + e) * 9 + pb] = f2tf(ba[e]);                     \
        const float* bb = (const float*)&b2v;                                    \
        _Pragma("unroll")                                                        \
        for (int e = 0; e < 4; e++)                                              \
            Bb[ksb*1152 + (bnq + 4 + e) * 9 + pb] = f2tf(bb[e]);                 \
    }

#define COMPUTE(BUF)                                                             \
    {                                                                            \
        uint32_t* Ab = As + (BUF)*2304;                                          \
        uint32_t* Bb = Bs + (BUF)*2304;                                          \
        _Pragma("unroll")                                                        \
        for (int ks = 0; ks < 2; ks++) {                                         \
            uint32_t af[4][4];                                                   \
            uint32_t bf[4][2];                                                   \
            _Pragma("unroll")                                                    \
            for (int mt = 0; mt < 4; mt++) {                                     \
                const uint32_t* pa  = &Ab[ks*1152 + (wm + mt*16 + g)*9 + 2*tg];  \
                const uint32_t* pa2 = &Ab[ks*1152 + (wm + mt*16 + g + 8)*9 + 2*tg];\
                af[mt][0] = pa[0]; af[mt][1] = pa2[0];                           \
                af[mt][2] = pa[1]; af[mt][3] = pa2[1];                           \
            }                                                                    \
            _Pragma("unroll")                                                    \
            for (int nt = 0; nt < 4; nt++) {                                     \
                const uint32_t* pbp = &Bb[ks*1152 + (wn + nt*8 + g)*9 + 2*tg];   \
                bf[nt][0] = pbp[0]; bf[nt][1] = pbp[1];                          \
            }                                                                    \
            _Pragma("unroll")                                                    \
            for (int mt = 0; mt < 4; mt++)                                       \
                _Pragma("unroll")                                                \
                for (int nt = 0; nt < 4; nt++)                                   \
                    mma8(acc[mt][nt], af[mt][0], af[mt][1], af[mt][2], af[mt][3],\
                         bf[nt][0], bf[nt][1]);                                  \
        }                                                                        \
    }

    STORE_TILE(0);
    __syncthreads();
    int buf = 0;
    for (int k0 = 16; k0 < 1024; k0 += 16) {
        a1v = *(const float4*)(Ap + k0);
        a2v = *(const float4*)(Ap + k0 + 4);
        b1v = *(const float4*)(Bp + (size_t)k0 * 1024);
        b2v = *(const float4*)(Bp + (size_t)k0 * 1024 + 4);
        COMPUTE(buf);
        buf ^= 1;
        STORE_TILE(buf);
        __syncthreads();
    }
    COMPUTE(buf);

#pragma unroll
    for (int mt = 0; mt < 4; mt++) {
#pragma unroll
        for (int nt = 0; nt < 4; nt++) {
            int m = bm + wm + mt*16 + g;
            int n = bn + wn + nt*8 + 2*tg;
            float2 v0 = make_float2(acc[mt][nt][0], acc[mt][nt][1]);
            float2 v1 = make_float2(acc[mt][nt][2], acc[mt][nt][3]);
            if (mode == 0) {
                *(float2*)&C[(size_t)m*1024 + n] = v0;
                *(float2*)&C[(size_t)(m+8)*1024 + n] = v1;
            } else {
                size_t b0i = ((size_t)(n >> 6)*LQ + m)*DHD + (n & 63);
                size_t b1i = ((size_t)(n >> 6)*LQ + m + 8)*DHD + (n & 63);
                *(float2*)&C[b0i] = v0;
                *(float2*)&C[b1i] = v1;
            }
        }
    }
#undef STORE_TILE
#undef COMPUTE
}

__global__ void __launch_bounds__(256, 2)
gemm_qkv(const float* __restrict__ A,
         const float* __restrict__ Wq, const float* __restrict__ Wk,
         const float* __restrict__ Wv,
         float* __restrict__ Cq, float* __restrict__ Ck, float* __restrict__ Cv) {
    __shared__ uint32_t As[2*2*1152];
    __shared__ uint32_t Bs[2*2*1152];
    int z = blockIdx.z;
    const float* B = (z == 0) ? Wq : (z == 1) ? Wk : Wv;
    float* C = (z == 0) ? Cq : (z == 1) ? Ck : Cv;
    gemm_core(A, B, C, 1, As, Bs);
}

__global__ void __launch_bounds__(256, 2)
gemm_ow(const float* __restrict__ Ao, const float* __restrict__ Wo,
        float* __restrict__ Co,
        const float* __restrict__ Ag, const float* __restrict__ Wg,
        float* __restrict__ Cg) {
    __shared__ uint32_t As[2*2*1152];
    __shared__ uint32_t Bs[2*2*1152];
    int z = blockIdx.z;
    const float* A = (z == 0) ? Ao : Ag;
    const float* B = (z == 0) ? Wo : Wg;
    float* C = (z == 0) ? Co : Cg;
    gemm_core(A, B, C, 0, As, Bs);
}

// ---------------- RoPE on q,k,v ----------------
__global__ void rope_kernel() {
    int idx = blockIdx.x * blockDim.x + threadIdx.x;   // NH*LQ*8
    int pair = idx & 7;
    int rest = idx >> 3;
    int l = rest & (LQ - 1);
    int base = rest * DHD;
    float invf = powf(10000.f, -(float)pair * 0.125f);
    float ang = (float)l * invf;
    float s, c;
    sincosf(ang, &s, &c);
    float a, b;
    a = g_q[base + pair]; b = g_q[base + pair + 8];
    g_q[base + pair] = a*c - b*s; g_q[base + pair + 8] = b*c + a*s;
    a = g_k[base + pair]; b = g_k[base + pair + 8];
    g_k[base + pair] = a*c - b*s; g_k[base + pair + 8] = b*c + a*s;
    a = g_v[base + pair]; b = g_v[base + pair + 8];
    g_v[base + pair] = a*c - b*s; g_v[base + pair + 8] = b*c + a*s;
}

// ---------------- QK: dots + per-row exp-sum partials ----------------
// 128x128 tile. No max subtraction (dots bounded; exp(-1e9)=0).
__global__ void __launch_bounds__(256, 2)
qk_tf32(const float* __restrict__ prev, float* __restrict__ dots) {
    extern __shared__ uint32_t sm[];
    uint32_t* Qs = sm;              // [8][1152]
    uint32_t* Ks = sm + 9216;
    float* sparts = (float*)(sm + 18432);   // 512 floats
    int t = threadIdx.x;
    int h = blockIdx.z;
    int i0 = blockIdx.y * 128, j0 = blockIdx.x * 128;
    int lane = t & 31, wid = t >> 5;
    int g = lane >> 2, tg = lane & 3;
    int wm = (wid >> 2) * 64, wn = (wid & 3) * 32;

    const float* qh = g_q + (size_t)h*LQ*DHD;
    const float* kh = g_k + (size_t)h*LQ*DHD;

    int m = t & 127, hk = (t >> 7) * 32;
    const float* qrow = qh + (size_t)(i0 + m)*DHD + hk;
    const float* krow = kh + (size_t)(j0 + m)*DHD + hk;
#pragma unroll
    for (int q = 0; q < 8; q++) {
        float4 v = *(const float4*)(qrow + q*4);
        float4 w = *(const float4*)(krow + q*4);
        const float* vp = (const float*)&v;
        const float* wp = (const float*)&w;
#pragma unroll
        for (int e = 0; e < 4; e++) {
            int kk = hk + q*4 + e;
            Qs[(kk >> 3)*1152 + m*9 + POS(kk)] = f2tf(vp[e]);
            Ks[(kk >> 3)*1152 + m*9 + POS(kk)] = f2tf(wp[e]);
        }
    }
    __syncthreads();

    float acc[4][4][4];
#pragma unroll
    for (int i = 0; i < 4; i++)
#pragma unroll
        for (int j = 0; j < 4; j++)
#pragma unroll
            for (int q = 0; q < 4; q++) acc[i][j][q] = 0.f;

#pragma unroll
    for (int ks = 0; ks < 8; ks++) {
        uint32_t af[4][4];
        uint32_t bf[4][2];
#pragma unroll
        for (int mt = 0; mt < 4; mt++) {
            const uint32_t* pa  = &Qs[ks*1152 + (wm + mt*16 + g)*9 + 2*tg];
            const uint32_t* pa2 = &Qs[ks*1152 + (wm + mt*16 + g + 8)*9 + 2*tg];
            af[mt][0] = pa[0]; af[mt][1] = pa2[0];
            af[mt][2] = pa[1]; af[mt][3] = pa2[1];
        }
#pragma unroll
        for (int nt = 0; nt < 4; nt++) {
            const uint32_t* pbp = &Ks[ks*1152 + (wn + nt*8 + g)*9 + 2*tg];
            bf[nt][0] = pbp[0]; bf[nt][1] = pbp[1];
        }
#pragma unroll
        for (int mt = 0; mt < 4; mt++)
#pragma unroll
            for (int nt = 0; nt < 4; nt++)
                mma8(acc[mt][nt], af[mt][0], af[mt][1], af[mt][2], af[mt][3],
                     bf[nt][0], bf[nt][1]);
    }

    float slope = exp2f(-0.5f * (float)(h + 1));
    float s_t[4][2];
#pragma unroll
    for (int mt = 0; mt < 4; mt++) {
#pragma unroll
        for (int rr = 0; rr < 2; rr++) {
            int gi = i0 + wm + mt*16 + g + rr*8;
            size_t rowb = ((size_t)(h*LQ + gi))*LQ;
            float vals[8];
#pragma unroll
            for (int nt = 0; nt < 4; nt++) {
                int j = j0 + wn + nt*8 + 2*tg;
                float2 pv = *(const float2*)&prev[rowb + j];
                int rel0 = gi - j, rel1 = gi - (j + 1);
                float2 ov;
                ov.x = acc[mt][nt][rr*2+0]*0.125f + pv.x +
                       ((rel0 >= 0) ? (-slope*(float)rel0) : -1000000000.0f);
                ov.y = acc[mt][nt][rr*2+1]*0.125f + pv.y +
                       ((rel1 >= 0) ? (-slope*(float)rel1) : -1000000000.0f);
                *(float2*)&dots[rowb + j] = ov;
                vals[nt*2]   = ov.x;
                vals[nt*2+1] = ov.y;
            }
            float ssum = 0.f;
#pragma unroll
            for (int q = 0; q < 8; q++) ssum += __expf(vals[q]);
            s_t[mt][rr] = ssum;
        }
    }

    // reduce within quad, then across the 4 n-warps
#pragma unroll
    for (int mt = 0; mt < 4; mt++) {
#pragma unroll
        for (int rr = 0; rr < 2; rr++) {
            float s = s_t[mt][rr];
            s += __shfl_xor_sync(0xffffffffu, s, 1);
            s += __shfl_xor_sync(0xffffffffu, s, 2);
            if (tg == 0)
                sparts[(wid & 3)*128 + wm + mt*16 + g + rr*8] = s;
        }
    }
    __syncthreads();
    if (t < 128) {
        float S = sparts[t] + sparts[128 + t] + sparts[256 + t] + sparts[384 + t];
        g_part[((size_t)(h*LQ + i0 + t))*16 + blockIdx.x] = S;
    }
}

// ---------------- row-sum finalize ----------------
__global__ void sumk_kernel() {
    int r = blockIdx.x * 256 + threadIdx.x;   // NH*LQ rows
    const float4* p = (const float4*)&g_part[(size_t)r * 16];
    float4 a = p[0], b = p[1], c = p[2], d = p[3];
    float s = a.x+a.y+a.z+a.w + b.x+b.y+b.z+b.w
            + c.x+c.y+c.z+c.w + d.x+d.y+d.z+d.w;
    g_sinv[r] = 1.f / s;
}

// ---------------- AV fused with prob computation ----------------
// CTA = (128 i-rows, head). Live chunks: read dots, p=exp(d)*Sinv, write attn,
// stage+MMA. Masked chunks: store zeros to attn only.
__global__ void __launch_bounds__(256, 2)
av_fused(const float* __restrict__ dots, float* __restrict__ attn) {
    extern __shared__ uint32_t sm2[];
    uint32_t* Ps = sm2;          // 8*1152 = 9216
    uint32_t* Vs = sm2 + 9216;   // 8*576  = 4608
    int t = threadIdx.x;
    int h = blockIdx.y;
    int i0 = ((int)gridDim.x - 1 - (int)blockIdx.x) * 128;
    int lane = t & 31, wid = t >> 5;
    int g = lane >> 2, tg = lane & 3;
    int wm2 = wid * 16;

    const float* vh = g_v + (size_t)h*LQ*DHD;
    int prow = t >> 1, pc0 = (t & 1) * 32;
    int vj = t >> 2, vd0 = (t & 3) * 16;
    float Si = g_sinv[h*LQ + i0 + prow];
    size_t rowbase = ((size_t)(h*LQ + i0 + prow))*LQ + pc0;

    float oacc[8][4];
#pragma unroll
    for (int i = 0; i < 8; i++)
#pragma unroll
        for (int q = 0; q < 4; q++) oacc[i][q] = 0.f;

    int nlive = i0/64 + 2;            // chunks of 64 containing any live j
    float4 dbuf[8];
    float4 vbuf[4];
    {
        const float* dp = &dots[rowbase];
#pragma unroll
        for (int q = 0; q < 8; q++) dbuf[q] = *(const float4*)(dp + q*4);
        const float* vr = vh + (size_t)vj*DHD + vd0;
#pragma unroll
        for (int q = 0; q < 4; q++) vbuf[q] = *(const float4*)(vr + q*4);
    }

    for (int c = 0; c < nlive; c++) {
        int jc = c * 64;
        // probs: exp * Sinv; write attn; stage P
#pragma unroll
        for (int q = 0; q < 8; q++) {
            float4 dv = dbuf[q];
            float4 p;
            p.x = __expf(dv.x) * Si;
            p.y = __expf(dv.y) * Si;
            p.z = __expf(dv.z) * Si;
            p.w = __expf(dv.w) * Si;
            *(float4*)&attn[rowbase + jc + q*4] = p;
            const float* pp = (const float*)&p;
#pragma unroll
            for (int e = 0; e < 4; e++) {
                int cc = pc0 + q*4 + e;
                Ps[(cc >> 3)*1152 + prow*9 + POS(cc & 7)] = f2tf(pp[e]);
            }
        }
        // stage V
#pragma unroll
        for (int q = 0; q < 4; q++) {
            float4 vv = vbuf[q];
            const float* wp = (const float*)&vv;
#pragma unroll
            for (int e = 0; e < 4; e++) {
                int d = vd0 + q*4 + e;
                Vs[(vj >> 3)*576 + d*9 + POS(vj & 7)] = f2tf(wp[e]);
            }
        }
        __syncthreads();
        // prefetch next live chunk under the MMA
        if (c + 1 < nlive) {
            int jn = jc + 64;
            const float* dp = &dots[rowbase + jn];
#pragma unroll
            for (int q = 0; q < 8; q++) dbuf[q] = *(const float4*)(dp + q*4);
            const float* vr = vh + (size_t)(jn + vj)*DHD + vd0;
#pragma unroll
            for (int q = 0; q < 4; q++) vbuf[q] = *(const float4*)(vr + q*4);
        }
#pragma unroll
        for (int ks = 0; ks < 8; ks++) {
            const uint32_t* pa  = &Ps[ks*1152 + (wm2 + g)*9 + 2*tg];
            const uint32_t* pa2 = &Ps[ks*1152 + (wm2 + g + 8)*9 + 2*tg];
            uint32_t a0 = pa[0], a1 = pa2[0], a2 = pa[1], a3 = pa2[1];
#pragma unroll
            for (int nt = 0; nt < 8; nt++) {
                const uint32_t* pbp = &Vs[ks*576 + (nt*8 + g)*9 + 2*tg];
                mma8(oacc[nt], a0, a1, a2, a3, pbp[0], pbp[1]);
            }
        }
        __syncthreads();
    }

    // masked region: attn = 0 (no dots read needed)
    float4 z = make_float4(0.f, 0.f, 0.f, 0.f);
    for (int jc = nlive*64; jc < LQ; jc += 64) {
#pragma unroll
        for (int q = 0; q < 8; q++)
            *(float4*)&attn[rowbase + jc + q*4] = z;
    }

#pragma unroll
    for (int nt = 0; nt < 8; nt++) {
        int d = nt*8 + 2*tg;
        int i = i0 + wm2 + g;
        *(float2*)&g_o[(size_t)i*DD + h*DHD + d] =
            make_float2(oacc[nt][0], oacc[nt][1]);
        *(float2*)&g_o[(size_t)(i+8)*DD + h*DHD + d] =
            make_float2(oacc[nt][2], oacc[nt][3]);
    }
}

// ---------------- final: y = sigmoid(x@Wg+bg) * (o@Wo+bo) + x ----------------
__global__ void final_kernel(const float* __restrict__ x,
                             const float* __restrict__ bo,
                             const float* __restrict__ bg,
                             float* __restrict__ y) {
    int idx = blockIdx.x * 256 + threadIdx.x;
    int n = idx & (DD - 1);
    float yo = g_yo[idx] + bo[n];
    float gg = g_gg[idx] + bg[n];
    float gate = 1.f / (1.f + __expf(-gg));
    y[idx] = gate * yo + x[idx];
}

extern "C" void kernel_launch(void* const* d_in, const int* in_sizes, int n_in,
                              void* d_out, int out_size) {
    const float* x     = (const float*)d_in[0];
    const float* prev  = (const float*)d_in[1];
    const float* Wq    = (const float*)d_in[2];
    const float* Wk    = (const float*)d_in[3];
    const float* Wv    = (const float*)d_in[4];
    const float* Wo    = (const float*)d_in[5];
    const float* bo    = (const float*)d_in[6];
    const float* gamma = (const float*)d_in[7];
    const float* beta  = (const float*)d_in[8];
    const float* Wg    = (const float*)d_in[9];
    const float* bg    = (const float*)d_in[10];

    float* y    = (float*)d_out;
    float* attn = y + (size_t)LQ * DD;
    float* dots = attn + (size_t)NH * LQ * LQ;

    float *ph, *pq, *pk, *pv, *po, *pyo, *pgg;
    cudaGetSymbolAddress((void**)&ph,  g_h);
    cudaGetSymbolAddress((void**)&pq,  g_q);
    cudaGetSymbolAddress((void**)&pk,  g_k);
    cudaGetSymbolAddress((void**)&pv,  g_v);
    cudaGetSymbolAddress((void**)&po,  g_o);
    cudaGetSymbolAddress((void**)&pyo, g_yo);
    cudaGetSymbolAddress((void**)&pgg, g_gg);

    size_t qsmb = (size_t)(2*9216 + 512) * sizeof(uint32_t);
    cudaFuncSetAttribute(qk_tf32, cudaFuncAttributeMaxDynamicSharedMemorySize, (int)qsmb);
    size_t avsmb = (size_t)(9216 + 4608) * sizeof(uint32_t);
    cudaFuncSetAttribute(av_fused, cudaFuncAttributeMaxDynamicSharedMemorySize, (int)avsmb);

    ln_kernel<<<LQ, 256>>>(x, gamma, beta);

    gemm_qkv<<<dim3(8, 16, 3), 256>>>(ph, Wq, Wk, Wv, pq, pk, pv);

    rope_kernel<<<(NH*LQ*8)/256, 256>>>();

    qk_tf32<<<dim3(16, 16, 16), 256, qsmb>>>(prev, dots);
    sumk_kernel<<<(NH*LQ)/256, 256>>>();
    av_fused<<<dim3(16, 16), 256, avsmb>>>(dots, attn);

    gemm_ow<<<dim3(8, 16, 2), 256>>>(po, Wo, pyo, x, Wg, pgg);

    final_kernel<<<(LQ*DD)/256, 256>>>(x, bo, bg, y);
}

// round 9
// speedup vs baseline: 1.0532x; 1.0325x over previous
#include <cuda_runtime.h>
#include <math.h>
#include <stdint.h>

#define LQ 2048
#define DD 1024
#define NH 16
#define DHD 64

__device__ float g_h [LQ*DD];
__device__ float g_q [NH*LQ*DHD];
__device__ float g_k [NH*LQ*DHD];
__device__ float g_v [NH*LQ*DHD];
__device__ float g_o [LQ*DD];
__device__ float g_yo[LQ*DD];
__device__ float g_gg[LQ*DD];
__device__ float g_part[NH*LQ*16];
__device__ float g_sinv[NH*LQ];

__device__ __forceinline__ uint32_t f2tf(float f) {
    uint32_t u;
    asm("cvt.rna.tf32.f32 %0, %1;" : "=r"(u) : "f"(f));
    return u;
}

__device__ __forceinline__ void mma8(float* c,
                                     uint32_t a0, uint32_t a1, uint32_t a2, uint32_t a3,
                                     uint32_t b0, uint32_t b1) {
    asm volatile("mma.sync.aligned.m16n8k8.row.col.f32.tf32.tf32.f32 "
        "{%0,%1,%2,%3}, {%4,%5,%6,%7}, {%8,%9}, {%0,%1,%2,%3};"
        : "+f"(c[0]), "+f"(c[1]), "+f"(c[2]), "+f"(c[3])
        : "r"(a0), "r"(a1), "r"(a2), "r"(a3), "r"(b0), "r"(b1));
}

#define POS(k) ((((k) & 3) * 2) + ((((k) >> 2) & 1)))

// ---------------- LayerNorm ----------------
__global__ void ln_kernel(const float* __restrict__ x,
                          const float* __restrict__ gamma,
                          const float* __restrict__ beta) {
    __shared__ float red[8];
    int row = blockIdx.x;
    int t = threadIdx.x;
    const float* xr = x + (size_t)row * DD;
    float v[4];
    float s = 0.f;
#pragma unroll
    for (int i = 0; i < 4; i++) { v[i] = xr[t + 256*i]; s += v[i]; }
#pragma unroll
    for (int o = 16; o; o >>= 1) s += __shfl_xor_sync(0xffffffffu, s, o);
    if ((t & 31) == 0) red[t >> 5] = s;
    __syncthreads();
    float tot = 0.f;
#pragma unroll
    for (int w = 0; w < 8; w++) tot += red[w];
    float mean = tot * (1.f / DD);
    __syncthreads();
    float s2 = 0.f;
#pragma unroll
    for (int i = 0; i < 4; i++) { float d = v[i] - mean; s2 += d*d; }
#pragma unroll
    for (int o = 16; o; o >>= 1) s2 += __shfl_xor_sync(0xffffffffu, s2, o);
    if ((t & 31) == 0) red[t >> 5] = s2;
    __syncthreads();
    float tot2 = 0.f;
#pragma unroll
    for (int w = 0; w < 8; w++) tot2 += red[w];
    float inv = rsqrtf(tot2 * (1.f / DD) + 1e-5f);
#pragma unroll
    for (int i = 0; i < 4; i++) {
        int c = t + 256*i;
        g_h[(size_t)row*DD + c] = (v[i] - mean) * inv * gamma[c] + beta[c];
    }
}

// ---------------- tf32 GEMM core (128x128, kc=16, double-buffered) ----------------
__device__ __forceinline__ void gemm_core(const float* __restrict__ A,
                                          const float* __restrict__ B,
                                          float* __restrict__ C, int mode,
                                          uint32_t* As, uint32_t* Bs) {
    int t = threadIdx.x;
    int bm = blockIdx.y * 128, bn = blockIdx.x * 128;
    int lane = t & 31, wid = t >> 5;
    int g = lane >> 2, tg = lane & 3;
    int wm = (wid >> 2) * 64, wn = (wid & 3) * 32;

    int am = t & 127, akq = (t >> 7) * 8;
    int bk = t & 15,  bnq = (t >> 4) * 8;
    int pb = POS(bk), ksb = bk >> 3;

    const float* Ap = A + (size_t)(bm + am) * 1024 + akq;
    const float* Bp = B + (size_t)bk * 1024 + bn + bnq;

    float acc[4][4][4];
#pragma unroll
    for (int i = 0; i < 4; i++)
#pragma unroll
        for (int j = 0; j < 4; j++)
#pragma unroll
            for (int q = 0; q < 4; q++) acc[i][j][q] = 0.f;

    float4 a1v = *(const float4*)(Ap);
    float4 a2v = *(const float4*)(Ap + 4);
    float4 b1v = *(const float4*)(Bp);
    float4 b2v = *(const float4*)(Bp + 4);

#define STORE_TILE(BUF)                                                          \
    {                                                                            \
        uint32_t* Ab = As + (BUF)*2304;                                          \
        uint32_t* Bb = Bs + (BUF)*2304;                                          \
        const float* aa = (const float*)&a1v;                                    \
        _Pragma("unroll")                                                        \
        for (int e = 0; e < 4; e++) {                                            \
            int kk = akq + e;                                                    \
            Ab[(kk >> 3)*1152 + am * 9 + POS(kk)] = f2tf(aa[e]);                 \
        }                                                                        \
        const float* ab = (const float*)&a2v;                                    \
        _Pragma("unroll")                                                        \
        for (int e = 0; e < 4; e++) {                                            \
            int kk = akq + 4 + e;                                                \
            Ab[(kk >> 3)*1152 + am * 9 + POS(kk)] = f2tf(ab[e]);                 \
        }                                                                        \
        const float* ba = (const float*)&b1v;                                    \
        _Pragma("unroll")                                                        \
        for (int e = 0; e < 4; e++)                                              \
            Bb[ksb*1152 + (bnq + e) * 9 + pb] = f2tf(ba[e]);                     \
        const float* bb = (const float*)&b2v;                                    \
        _Pragma("unroll")                                                        \
        for (int e = 0; e < 4; e++)                                              \
            Bb[ksb*1152 + (bnq + 4 + e) * 9 + pb] = f2tf(bb[e]);                 \
    }

#define COMPUTE(BUF)                                                             \
    {                                                                            \
        uint32_t* Ab = As + (BUF)*2304;                                          \
        uint32_t* Bb = Bs + (BUF)*2304;                                          \
        _Pragma("unroll")                                                        \
        for (int ks = 0; ks < 2; ks++) {                                         \
            uint32_t af[4][4];                                                   \
            uint32_t bf[4][2];                                                   \
            _Pragma("unroll")                                                    \
            for (int mt = 0; mt < 4; mt++) {                                     \
                const uint32_t* pa  = &Ab[ks*1152 + (wm + mt*16 + g)*9 + 2*tg];  \
                const uint32_t* pa2 = &Ab[ks*1152 + (wm + mt*16 + g + 8)*9 + 2*tg];\
                af[mt][0] = pa[0]; af[mt][1] = pa2[0];                           \
                af[mt][2] = pa[1]; af[mt][3] = pa2[1];                           \
            }                                                                    \
            _Pragma("unroll")                                                    \
            for (int nt = 0; nt < 4; nt++) {                                     \
                const uint32_t* pbp = &Bb[ks*1152 + (wn + nt*8 + g)*9 + 2*tg];   \
                bf[nt][0] = pbp[0]; bf[nt][1] = pbp[1];                          \
            }                                                                    \
            _Pragma("unroll")                                                    \
            for (int mt = 0; mt < 4; mt++)                                       \
                _Pragma("unroll")                                                \
                for (int nt = 0; nt < 4; nt++)                                   \
                    mma8(acc[mt][nt], af[mt][0], af[mt][1], af[mt][2], af[mt][3],\
                         bf[nt][0], bf[nt][1]);                                  \
        }                                                                        \
    }

    STORE_TILE(0);
    __syncthreads();
    int buf = 0;
    for (int k0 = 16; k0 < 1024; k0 += 16) {
        a1v = *(const float4*)(Ap + k0);
        a2v = *(const float4*)(Ap + k0 + 4);
        b1v = *(const float4*)(Bp + (size_t)k0 * 1024);
        b2v = *(const float4*)(Bp + (size_t)k0 * 1024 + 4);
        COMPUTE(buf);
        buf ^= 1;
        STORE_TILE(buf);
        __syncthreads();
    }
    COMPUTE(buf);

#pragma unroll
    for (int mt = 0; mt < 4; mt++) {
#pragma unroll
        for (int nt = 0; nt < 4; nt++) {
            int m = bm + wm + mt*16 + g;
            int n = bn + wn + nt*8 + 2*tg;
            float2 v0 = make_float2(acc[mt][nt][0], acc[mt][nt][1]);
            float2 v1 = make_float2(acc[mt][nt][2], acc[mt][nt][3]);
            if (mode == 0) {
                *(float2*)&C[(size_t)m*1024 + n] = v0;
                *(float2*)&C[(size_t)(m+8)*1024 + n] = v1;
            } else {
                size_t b0i = ((size_t)(n >> 6)*LQ + m)*DHD + (n & 63);
                size_t b1i = ((size_t)(n >> 6)*LQ + m + 8)*DHD + (n & 63);
                *(float2*)&C[b0i] = v0;
                *(float2*)&C[b1i] = v1;
            }
        }
    }
#undef STORE_TILE
#undef COMPUTE
}

__global__ void __launch_bounds__(256, 2)
gemm_qkv(const float* __restrict__ A,
         const float* __restrict__ Wq, const float* __restrict__ Wk,
         const float* __restrict__ Wv,
         float* __restrict__ Cq, float* __restrict__ Ck, float* __restrict__ Cv) {
    __shared__ uint32_t As[2*2*1152];
    __shared__ uint32_t Bs[2*2*1152];
    int z = blockIdx.z;
    const float* B = (z == 0) ? Wq : (z == 1) ? Wk : Wv;
    float* C = (z == 0) ? Cq : (z == 1) ? Ck : Cv;
    gemm_core(A, B, C, 1, As, Bs);
}

__global__ void __launch_bounds__(256, 2)
gemm_ow(const float* __restrict__ Ao, const float* __restrict__ Wo,
        float* __restrict__ Co,
        const float* __restrict__ Ag, const float* __restrict__ Wg,
        float* __restrict__ Cg) {
    __shared__ uint32_t As[2*2*1152];
    __shared__ uint32_t Bs[2*2*1152];
    int z = blockIdx.z;
    const float* A = (z == 0) ? Ao : Ag;
    const float* B = (z == 0) ? Wo : Wg;
    float* C = (z == 0) ? Co : Cg;
    gemm_core(A, B, C, 0, As, Bs);
}

// ---------------- RoPE on q,k,v ----------------
__global__ void rope_kernel() {
    int idx = blockIdx.x * blockDim.x + threadIdx.x;   // NH*LQ*8
    int pair = idx & 7;
    int rest = idx >> 3;
    int l = rest & (LQ - 1);
    int base = rest * DHD;
    float invf = powf(10000.f, -(float)pair * 0.125f);
    float ang = (float)l * invf;
    float s, c;
    sincosf(ang, &s, &c);
    float a, b;
    a = g_q[base + pair]; b = g_q[base + pair + 8];
    g_q[base + pair] = a*c - b*s; g_q[base + pair + 8] = b*c + a*s;
    a = g_k[base + pair]; b = g_k[base + pair + 8];
    g_k[base + pair] = a*c - b*s; g_k[base + pair + 8] = b*c + a*s;
    a = g_v[base + pair]; b = g_v[base + pair + 8];
    g_v[base + pair] = a*c - b*s; g_v[base + pair + 8] = b*c + a*s;
}

// ---------------- QK: dots + per-row exp-sum partials ----------------
// 128x128 tile. No max subtraction (dots bounded; exp(-1e9)=0).
// Fully-masked tiles (j0 > i0): dots = prev - 1e9 (S-term dropped: |S/8| << 1e9,
// rel err ~1e-8; exp()==0 either way so attn/o are exact). Pure streaming path.
__global__ void __launch_bounds__(256, 2)
qk_tf32(const float* __restrict__ prev, float* __restrict__ dots) {
    extern __shared__ uint32_t sm[];
    uint32_t* Qs = sm;              // [8][1152]
    uint32_t* Ks = sm + 9216;
    float* sparts = (float*)(sm + 18432);   // 512 floats
    int t = threadIdx.x;
    int h = blockIdx.z;
    int i0 = blockIdx.y * 128, j0 = blockIdx.x * 128;

    if (j0 > i0) {
        // fully-masked streaming tile
        int r = t >> 1;                     // 0..127
        int c0 = (t & 1) * 64;
        size_t rowb = ((size_t)(h*LQ + i0 + r))*LQ + j0 + c0;
#pragma unroll
        for (int q = 0; q < 16; q++) {
            float4 pv = *(const float4*)&prev[rowb + q*4];
            float4 ov;
            ov.x = pv.x - 1000000000.0f;
            ov.y = pv.y - 1000000000.0f;
            ov.z = pv.z - 1000000000.0f;
            ov.w = pv.w - 1000000000.0f;
            *(float4*)&dots[rowb + q*4] = ov;
        }
        if (t < 128)
            g_part[((size_t)(h*LQ + i0 + t))*16 + blockIdx.x] = 0.f;
        return;
    }

    int lane = t & 31, wid = t >> 5;
    int g = lane >> 2, tg = lane & 3;
    int wm = (wid >> 2) * 64, wn = (wid & 3) * 32;

    const float* qh = g_q + (size_t)h*LQ*DHD;
    const float* kh = g_k + (size_t)h*LQ*DHD;

    int m = t & 127, hk = (t >> 7) * 32;
    const float* qrow = qh + (size_t)(i0 + m)*DHD + hk;
    const float* krow = kh + (size_t)(j0 + m)*DHD + hk;
#pragma unroll
    for (int q = 0; q < 8; q++) {
        float4 v = *(const float4*)(qrow + q*4);
        float4 w = *(const float4*)(krow + q*4);
        const float* vp = (const float*)&v;
        const float* wp = (const float*)&w;
#pragma unroll
        for (int e = 0; e < 4; e++) {
            int kk = hk + q*4 + e;
            Qs[(kk >> 3)*1152 + m*9 + POS(kk)] = f2tf(vp[e]);
            Ks[(kk >> 3)*1152 + m*9 + POS(kk)] = f2tf(wp[e]);
        }
    }
    __syncthreads();

    float acc[4][4][4];
#pragma unroll
    for (int i = 0; i < 4; i++)
#pragma unroll
        for (int j = 0; j < 4; j++)
#pragma unroll
            for (int q = 0; q < 4; q++) acc[i][j][q] = 0.f;

#pragma unroll
    for (int ks = 0; ks < 8; ks++) {
        uint32_t af[4][4];
        uint32_t bf[4][2];
#pragma unroll
        for (int mt = 0; mt < 4; mt++) {
            const uint32_t* pa  = &Qs[ks*1152 + (wm + mt*16 + g)*9 + 2*tg];
            const uint32_t* pa2 = &Qs[ks*1152 + (wm + mt*16 + g + 8)*9 + 2*tg];
            af[mt][0] = pa[0]; af[mt][1] = pa2[0];
            af[mt][2] = pa[1]; af[mt][3] = pa2[1];
        }
#pragma unroll
        for (int nt = 0; nt < 4; nt++) {
            const uint32_t* pbp = &Ks[ks*1152 + (wn + nt*8 + g)*9 + 2*tg];
            bf[nt][0] = pbp[0]; bf[nt][1] = pbp[1];
        }
#pragma unroll
        for (int mt = 0; mt < 4; mt++)
#pragma unroll
            for (int nt = 0; nt < 4; nt++)
                mma8(acc[mt][nt], af[mt][0], af[mt][1], af[mt][2], af[mt][3],
                     bf[nt][0], bf[nt][1]);
    }

    float slope = exp2f(-0.5f * (float)(h + 1));
    float s_t[4][2];
#pragma unroll
    for (int mt = 0; mt < 4; mt++) {
#pragma unroll
        for (int rr = 0; rr < 2; rr++) {
            int gi = i0 + wm + mt*16 + g + rr*8;
            size_t rowb = ((size_t)(h*LQ + gi))*LQ;
            float vals[8];
#pragma unroll
            for (int nt = 0; nt < 4; nt++) {
                int j = j0 + wn + nt*8 + 2*tg;
                float2 pv = *(const float2*)&prev[rowb + j];
                int rel0 = gi - j, rel1 = gi - (j + 1);
                float2 ov;
                ov.x = acc[mt][nt][rr*2+0]*0.125f + pv.x +
                       ((rel0 >= 0) ? (-slope*(float)rel0) : -1000000000.0f);
                ov.y = acc[mt][nt][rr*2+1]*0.125f + pv.y +
                       ((rel1 >= 0) ? (-slope*(float)rel1) : -1000000000.0f);
                *(float2*)&dots[rowb + j] = ov;
                vals[nt*2]   = ov.x;
                vals[nt*2+1] = ov.y;
            }
            float ssum = 0.f;
#pragma unroll
            for (int q = 0; q < 8; q++) ssum += __expf(vals[q]);
            s_t[mt][rr] = ssum;
        }
    }

    // reduce within quad, then across the 4 n-warps
#pragma unroll
    for (int mt = 0; mt < 4; mt++) {
#pragma unroll
        for (int rr = 0; rr < 2; rr++) {
            float s = s_t[mt][rr];
            s += __shfl_xor_sync(0xffffffffu, s, 1);
            s += __shfl_xor_sync(0xffffffffu, s, 2);
            if (tg == 0)
                sparts[(wid & 3)*128 + wm + mt*16 + g + rr*8] = s;
        }
    }
    __syncthreads();
    if (t < 128) {
        float S = sparts[t] + sparts[128 + t] + sparts[256 + t] + sparts[384 + t];
        g_part[((size_t)(h*LQ + i0 + t))*16 + blockIdx.x] = S;
    }
}

// ---------------- row-sum finalize ----------------
__global__ void sumk_kernel() {
    int r = blockIdx.x * 256 + threadIdx.x;   // NH*LQ rows
    const float4* p = (const float4*)&g_part[(size_t)r * 16];
    float4 a = p[0], b = p[1], c = p[2], d = p[3];
    float s = a.x+a.y+a.z+a.w + b.x+b.y+b.z+b.w
            + c.x+c.y+c.z+c.w + d.x+d.y+d.z+d.w;
    g_sinv[r] = 1.f / s;
}

// ---------------- AV fused with prob computation ----------------
__global__ void __launch_bounds__(256, 2)
av_fused(const float* __restrict__ dots, float* __restrict__ attn) {
    extern __shared__ uint32_t sm2[];
    uint32_t* Ps = sm2;          // 8*1152 = 9216
    uint32_t* Vs = sm2 + 9216;   // 8*576  = 4608
    int t = threadIdx.x;
    int h = blockIdx.y;
    int i0 = ((int)gridDim.x - 1 - (int)blockIdx.x) * 128;
    int lane = t & 31, wid = t >> 5;
    int g = lane >> 2, tg = lane & 3;
    int wm2 = wid * 16;

    const float* vh = g_v + (size_t)h*LQ*DHD;
    int prow = t >> 1, pc0 = (t & 1) * 32;
    int vj = t >> 2, vd0 = (t & 3) * 16;
    float Si = g_sinv[h*LQ + i0 + prow];
    size_t rowbase = ((size_t)(h*LQ + i0 + prow))*LQ + pc0;

    float oacc[8][4];
#pragma unroll
    for (int i = 0; i < 8; i++)
#pragma unroll
        for (int q = 0; q < 4; q++) oacc[i][q] = 0.f;

    int nlive = i0/64 + 2;
    float4 dbuf[8];
    float4 vbuf[4];
    {
        const float* dp = &dots[rowbase];
#pragma unroll
        for (int q = 0; q < 8; q++) dbuf[q] = *(const float4*)(dp + q*4);
        const float* vr = vh + (size_t)vj*DHD + vd0;
#pragma unroll
        for (int q = 0; q < 4; q++) vbuf[q] = *(const float4*)(vr + q*4);
    }

    for (int c = 0; c < nlive; c++) {
        int jc = c * 64;
#pragma unroll
        for (int q = 0; q < 8; q++) {
            float4 dv = dbuf[q];
            float4 p;
            p.x = __expf(dv.x) * Si;
            p.y = __expf(dv.y) * Si;
            p.z = __expf(dv.z) * Si;
            p.w = __expf(dv.w) * Si;
            *(float4*)&attn[rowbase + jc + q*4] = p;
            const float* pp = (const float*)&p;
#pragma unroll
            for (int e = 0; e < 4; e++) {
                int cc = pc0 + q*4 + e;
                Ps[(cc >> 3)*1152 + prow*9 + POS(cc & 7)] = f2tf(pp[e]);
            }
        }
#pragma unroll
        for (int q = 0; q < 4; q++) {
            float4 vv = vbuf[q];
            const float* wp = (const float*)&vv;
#pragma unroll
            for (int e = 0; e < 4; e++) {
                int d = vd0 + q*4 + e;
                Vs[(vj >> 3)*576 + d*9 + POS(vj & 7)] = f2tf(wp[e]);
            }
        }
        __syncthreads();
        if (c + 1 < nlive) {
            int jn = jc + 64;
            const float* dp = &dots[rowbase + jn];
#pragma unroll
            for (int q = 0; q < 8; q++) dbuf[q] = *(const float4*)(dp + q*4);
            const float* vr = vh + (size_t)(jn + vj)*DHD + vd0;
#pragma unroll
            for (int q = 0; q < 4; q++) vbuf[q] = *(const float4*)(vr + q*4);
        }
#pragma unroll
        for (int ks = 0; ks < 8; ks++) {
            const uint32_t* pa  = &Ps[ks*1152 + (wm2 + g)*9 + 2*tg];
            const uint32_t* pa2 = &Ps[ks*1152 + (wm2 + g + 8)*9 + 2*tg];
            uint32_t a0 = pa[0], a1 = pa2[0], a2 = pa[1], a3 = pa2[1];
#pragma unroll
            for (int nt = 0; nt < 8; nt++) {
                const uint32_t* pbp = &Vs[ks*576 + (nt*8 + g)*9 + 2*tg];
                mma8(oacc[nt], a0, a1, a2, a3, pbp[0], pbp[1]);
            }
        }
        __syncthreads();
    }

    float4 z = make_float4(0.f, 0.f, 0.f, 0.f);
    for (int jc = nlive*64; jc < LQ; jc += 64) {
#pragma unroll
        for (int q = 0; q < 8; q++)
            *(float4*)&attn[rowbase + jc + q*4] = z;
    }

#pragma unroll
    for (int nt = 0; nt < 8; nt++) {
        int d = nt*8 + 2*tg;
        int i = i0 + wm2 + g;
        *(float2*)&g_o[(size_t)i*DD + h*DHD + d] =
            make_float2(oacc[nt][0], oacc[nt][1]);
        *(float2*)&g_o[(size_t)(i+8)*DD + h*DHD + d] =
            make_float2(oacc[nt][2], oacc[nt][3]);
    }
}

// ---------------- final: y = sigmoid(x@Wg+bg) * (o@Wo+bo) + x ----------------
__global__ void final_kernel(const float* __restrict__ x,
                             const float* __restrict__ bo,
                             const float* __restrict__ bg,
                             float* __restrict__ y) {
    int idx = blockIdx.x * 256 + threadIdx.x;
    int n = idx & (DD - 1);
    float yo = g_yo[idx] + bo[n];
    float gg = g_gg[idx] + bg[n];
    float gate = 1.f / (1.f + __expf(-gg));
    y[idx] = gate * yo + x[idx];
}

extern "C" void kernel_launch(void* const* d_in, const int* in_sizes, int n_in,
                              void* d_out, int out_size) {
    const float* x     = (const float*)d_in[0];
    const float* prev  = (const float*)d_in[1];
    const float* Wq    = (const float*)d_in[2];
    const float* Wk    = (const float*)d_in[3];
    const float* Wv    = (const float*)d_in[4];
    const float* Wo    = (const float*)d_in[5];
    const float* bo    = (const float*)d_in[6];
    const float* gamma = (const float*)d_in[7];
    const float* beta  = (const float*)d_in[8];
    const float* Wg    = (const float*)d_in[9];
    const float* bg    = (const float*)d_in[10];

    float* y    = (float*)d_out;
    float* attn = y + (size_t)LQ * DD;
    float* dots = attn + (size_t)NH * LQ * LQ;

    float *ph, *pq, *pk, *pv, *po, *pyo, *pgg;
    cudaGetSymbolAddress((void**)&ph,  g_h);
    cudaGetSymbolAddress((void**)&pq,  g_q);
    cudaGetSymbolAddress((void**)&pk,  g_k);
    cudaGetSymbolAddress((void**)&pv,  g_v);
    cudaGetSymbolAddress((void**)&po,  g_o);
    cudaGetSymbolAddress((void**)&pyo, g_yo);
    cudaGetSymbolAddress((void**)&pgg, g_gg);

    size_t qsmb = (size_t)(2*9216 + 512) * sizeof(uint32_t);
    cudaFuncSetAttribute(qk_tf32, cudaFuncAttributeMaxDynamicSharedMemorySize, (int)qsmb);
    size_t avsmb = (size_t)(9216 + 4608) * sizeof(uint32_t);
    cudaFuncSetAttribute(av_fused, cudaFuncAttributeMaxDynamicSharedMemorySize, (int)avsmb);

    ln_kernel<<<LQ, 256>>>(x, gamma, beta);

    gemm_qkv<<<dim3(8, 16, 3), 256>>>(ph, Wq, Wk, Wv, pq, pk, pv);

    rope_kernel<<<(NH*LQ*8)/256, 256>>>();

    qk_tf32<<<dim3(16, 16, 16), 256, qsmb>>>(prev, dots);
    sumk_kernel<<<(NH*LQ)/256, 256>>>();
    av_fused<<<dim3(16, 16), 256, avsmb>>>(dots, attn);

    gemm_ow<<<dim3(8, 16, 2), 256>>>(po, Wo, pyo, x, Wg, pgg);

    final_kernel<<<(LQ*DD)/256, 256>>>(x, bo, bg, y);
}

// round 10
// speedup vs baseline: 1.3916x; 1.3213x over previous
#include <cuda_runtime.h>
#include <math.h>
#include <stdint.h>

#define LQ 2048
#define DD 1024
#define NH 16
#define DHD 64

__device__ float g_h [LQ*DD];
__device__ float g_q [NH*LQ*DHD];
__device__ float g_k [NH*LQ*DHD];
__device__ float g_v [NH*LQ*DHD];
__device__ float g_o [LQ*DD];
__device__ float g_yo[LQ*DD];
__device__ float g_gg[LQ*DD];
__device__ float g_part[NH*LQ*16];
__device__ float g_sinv[NH*LQ];

__device__ __forceinline__ void mma8(float* c,
                                     uint32_t a0, uint32_t a1, uint32_t a2, uint32_t a3,
                                     uint32_t b0, uint32_t b1) {
    asm volatile("mma.sync.aligned.m16n8k8.row.col.f32.tf32.tf32.f32 "
        "{%0,%1,%2,%3}, {%4,%5,%6,%7}, {%8,%9}, {%0,%1,%2,%3};"
        : "+f"(c[0]), "+f"(c[1]), "+f"(c[2]), "+f"(c[3])
        : "r"(a0), "r"(a1), "r"(a2), "r"(a3), "r"(b0), "r"(b1));
}

__device__ __forceinline__ uint32_t smem_u32(const void* p) {
    return (uint32_t)__cvta_generic_to_shared(p);
}
#define CP16(dst_u32, src_ptr) \
    asm volatile("cp.async.cg.shared.global [%0], [%1], 16;" :: "r"(dst_u32), "l"(src_ptr))
#define CP_COMMIT() asm volatile("cp.async.commit_group;")
#define CP_WAIT(n)  asm volatile("cp.async.wait_group %0;" :: "n"(n))

// ---------------- LayerNorm ----------------
__global__ void ln_kernel(const float* __restrict__ x,
                          const float* __restrict__ gamma,
                          const float* __restrict__ beta) {
    __shared__ float red[8];
    int row = blockIdx.x;
    int t = threadIdx.x;
    const float* xr = x + (size_t)row * DD;
    float v[4];
    float s = 0.f;
#pragma unroll
    for (int i = 0; i < 4; i++) { v[i] = xr[t + 256*i]; s += v[i]; }
#pragma unroll
    for (int o = 16; o; o >>= 1) s += __shfl_xor_sync(0xffffffffu, s, o);
    if ((t & 31) == 0) red[t >> 5] = s;
    __syncthreads();
    float tot = 0.f;
#pragma unroll
    for (int w = 0; w < 8; w++) tot += red[w];
    float mean = tot * (1.f / DD);
    __syncthreads();
    float s2 = 0.f;
#pragma unroll
    for (int i = 0; i < 4; i++) { float d = v[i] - mean; s2 += d*d; }
#pragma unroll
    for (int o = 16; o; o >>= 1) s2 += __shfl_xor_sync(0xffffffffu, s2, o);
    if ((t & 31) == 0) red[t >> 5] = s2;
    __syncthreads();
    float tot2 = 0.f;
#pragma unroll
    for (int w = 0; w < 8; w++) tot2 += red[w];
    float inv = rsqrtf(tot2 * (1.f / DD) + 1e-5f);
#pragma unroll
    for (int i = 0; i < 4; i++) {
        int c = t + 256*i;
        g_h[(size_t)row*DD + c] = (v[i] - mean) * inv * gamma[c] + beta[c];
    }
}

// ---------------- tf32 GEMM core: linear smem + cp.async 3-stage ----------------
#define AST 20
#define BST 136
#define ATILE (128*AST)   // 2560 words
#define BTILE (16*BST)    // 2176 words

__device__ __forceinline__ void gemm_core(const float* __restrict__ A,
                                          const float* __restrict__ B,
                                          float* __restrict__ C, int mode,
                                          uint32_t* sA, uint32_t* sB) {
    int t = threadIdx.x;
    int bm = blockIdx.y * 128, bn = blockIdx.x * 128;
    int lane = t & 31, wid = t >> 5;
    int g = lane >> 2, tg = lane & 3;
    int wm = (wid >> 2) * 64, wn = (wid & 3) * 32;

    int arow = t >> 1, ac0 = (t & 1) * 8;
    int brow = t & 15, bc0 = (t >> 4) * 8;
    const float* Abase = A + (size_t)(bm + arow)*1024 + ac0;
    const float* Bbase = B + (size_t)brow*1024 + bn + bc0;
    uint32_t sAa = smem_u32(sA) + (uint32_t)(arow*AST + ac0)*4;
    uint32_t sBa = smem_u32(sB) + (uint32_t)(brow*BST + bc0)*4;

    float acc[4][4][4];
#pragma unroll
    for (int i = 0; i < 4; i++)
#pragma unroll
        for (int j = 0; j < 4; j++)
#pragma unroll
            for (int q = 0; q < 4; q++) acc[i][j][q] = 0.f;

#define ISSUE(kt) {                                                      \
    int st_ = (kt) % 3; int k0_ = (kt) * 16;                             \
    CP16(sAa + st_*ATILE*4,      Abase + k0_);                           \
    CP16(sAa + st_*ATILE*4 + 16, Abase + k0_ + 4);                       \
    CP16(sBa + st_*BTILE*4,      Bbase + (size_t)k0_*1024);              \
    CP16(sBa + st_*BTILE*4 + 16, Bbase + (size_t)k0_*1024 + 4);          \
}

#define COMP(stg) {                                                      \
    const uint32_t* Ab = sA + (stg)*ATILE;                               \
    const uint32_t* Bb = sB + (stg)*BTILE;                               \
    _Pragma("unroll")                                                    \
    for (int ks = 0; ks < 2; ks++) {                                     \
        uint32_t af[4][4], bf[4][2];                                     \
        _Pragma("unroll")                                                \
        for (int mt = 0; mt < 4; mt++) {                                 \
            const uint32_t* pa = Ab + (wm + mt*16 + g)*AST + ks*8 + tg;  \
            af[mt][0] = pa[0];       af[mt][1] = pa[8*AST];              \
            af[mt][2] = pa[4];       af[mt][3] = pa[8*AST + 4];          \
        }                                                                \
        _Pragma("unroll")                                                \
        for (int nt = 0; nt < 4; nt++) {                                 \
            const uint32_t* pb = Bb + (ks*8 + tg)*BST + wn + nt*8 + g;   \
            bf[nt][0] = pb[0];       bf[nt][1] = pb[4*BST];              \
        }                                                                \
        _Pragma("unroll")                                                \
        for (int mt = 0; mt < 4; mt++)                                   \
            _Pragma("unroll")                                            \
            for (int nt = 0; nt < 4; nt++)                               \
                mma8(acc[mt][nt], af[mt][0], af[mt][1], af[mt][2],       \
                     af[mt][3], bf[nt][0], bf[nt][1]);                   \
    }                                                                    \
}

    ISSUE(0); CP_COMMIT();
    ISSUE(1); CP_COMMIT();
    for (int kt = 0; kt < 64; kt++) {
        CP_WAIT(1);
        __syncthreads();
        if (kt + 2 < 64) { ISSUE(kt + 2); }
        CP_COMMIT();
        COMP(kt % 3);
    }

#pragma unroll
    for (int mt = 0; mt < 4; mt++) {
#pragma unroll
        for (int nt = 0; nt < 4; nt++) {
            int m = bm + wm + mt*16 + g;
            int n = bn + wn + nt*8 + 2*tg;
            float2 v0 = make_float2(acc[mt][nt][0], acc[mt][nt][1]);
            float2 v1 = make_float2(acc[mt][nt][2], acc[mt][nt][3]);
            if (mode == 0) {
                *(float2*)&C[(size_t)m*1024 + n] = v0;
                *(float2*)&C[(size_t)(m+8)*1024 + n] = v1;
            } else {
                size_t b0i = ((size_t)(n >> 6)*LQ + m)*DHD + (n & 63);
                size_t b1i = ((size_t)(n >> 6)*LQ + m + 8)*DHD + (n & 63);
                *(float2*)&C[b0i] = v0;
                *(float2*)&C[b1i] = v1;
            }
        }
    }
#undef ISSUE
#undef COMP
}

#define GEMM_SMEM_WORDS (3*(ATILE + BTILE))   // 14208 words = 56832 B

__global__ void __launch_bounds__(256, 2)
gemm_qkv(const float* __restrict__ A,
         const float* __restrict__ Wq, const float* __restrict__ Wk,
         const float* __restrict__ Wv,
         float* __restrict__ Cq, float* __restrict__ Ck, float* __restrict__ Cv) {
    extern __shared__ uint32_t smg[];
    uint32_t* sA = smg;
    uint32_t* sB = smg + 3*ATILE;
    int z = blockIdx.z;
    const float* B = (z == 0) ? Wq : (z == 1) ? Wk : Wv;
    float* C = (z == 0) ? Cq : (z == 1) ? Ck : Cv;
    gemm_core(A, B, C, 1, sA, sB);
}

__global__ void __launch_bounds__(256, 2)
gemm_ow(const float* __restrict__ Ao, const float* __restrict__ Wo,
        float* __restrict__ Co,
        const float* __restrict__ Ag, const float* __restrict__ Wg,
        float* __restrict__ Cg) {
    extern __shared__ uint32_t smg[];
    uint32_t* sA = smg;
    uint32_t* sB = smg + 3*ATILE;
    int z = blockIdx.z;
    const float* A = (z == 0) ? Ao : Ag;
    const float* B = (z == 0) ? Wo : Wg;
    float* C = (z == 0) ? Co : Cg;
    gemm_core(A, B, C, 0, sA, sB);
}

// ---------------- RoPE on q,k,v ----------------
__global__ void rope_kernel() {
    int idx = blockIdx.x * blockDim.x + threadIdx.x;   // NH*LQ*8
    int pair = idx & 7;
    int rest = idx >> 3;
    int l = rest & (LQ - 1);
    int base = rest * DHD;
    float invf = powf(10000.f, -(float)pair * 0.125f);
    float ang = (float)l * invf;
    float s, c;
    sincosf(ang, &s, &c);
    float a, b;
    a = g_q[base + pair]; b = g_q[base + pair + 8];
    g_q[base + pair] = a*c - b*s; g_q[base + pair + 8] = b*c + a*s;
    a = g_k[base + pair]; b = g_k[base + pair + 8];
    g_k[base + pair] = a*c - b*s; g_k[base + pair + 8] = b*c + a*s;
    a = g_v[base + pair]; b = g_v[base + pair + 8];
    g_v[base + pair] = a*c - b*s; g_v[base + pair + 8] = b*c + a*s;
}

// ---------------- QK: dots + per-row exp-sum partials ----------------
#define QST 68
#define QK_SMEM_WORDS (2*128*QST + 512)   // 17920 words = 71680 B
__global__ void __launch_bounds__(256, 2)
qk_tf32(const float* __restrict__ prev, float* __restrict__ dots) {
    extern __shared__ uint32_t sm[];
    uint32_t* Qs = sm;                 // [128][68]
    uint32_t* Ks = sm + 128*QST;
    float* sparts = (float*)(sm + 2*128*QST);   // 512 floats
    int t = threadIdx.x;
    int h = blockIdx.z;
    int i0 = blockIdx.y * 128, j0 = blockIdx.x * 128;

    if (j0 > i0) {
        // fully-masked streaming tile: dots = prev - 1e9 (S-term negligible)
        int r = t >> 1;
        int c0 = (t & 1) * 64;
        size_t rowb = ((size_t)(h*LQ + i0 + r))*LQ + j0 + c0;
#pragma unroll
        for (int q = 0; q < 16; q++) {
            float4 pv = *(const float4*)&prev[rowb + q*4];
            float4 ov;
            ov.x = pv.x - 1000000000.0f;
            ov.y = pv.y - 1000000000.0f;
            ov.z = pv.z - 1000000000.0f;
            ov.w = pv.w - 1000000000.0f;
            *(float4*)&dots[rowb + q*4] = ov;
        }
        if (t < 128)
            g_part[((size_t)(h*LQ + i0 + t))*16 + blockIdx.x] = 0.f;
        return;
    }

    int lane = t & 31, wid = t >> 5;
    int g = lane >> 2, tg = lane & 3;
    int wm = (wid >> 2) * 64, wn = (wid & 3) * 32;

    const float* qh = g_q + (size_t)h*LQ*DHD;
    const float* kh = g_k + (size_t)h*LQ*DHD;

    // stage Q,K via cp.async: row = t>>1, cols (t&1)*32 .. +31
    {
        int m = t >> 1, cb = (t & 1) * 32;
        const float* qsrc = qh + (size_t)(i0 + m)*DHD + cb;
        const float* ksrc = kh + (size_t)(j0 + m)*DHD + cb;
        uint32_t qdst = smem_u32(Qs) + (uint32_t)(m*QST + cb)*4;
        uint32_t kdst = smem_u32(Ks) + (uint32_t)(m*QST + cb)*4;
#pragma unroll
        for (int q = 0; q < 8; q++) {
            CP16(qdst + q*16, qsrc + q*4);
            CP16(kdst + q*16, ksrc + q*4);
        }
        CP_COMMIT();
    }
    CP_WAIT(0);
    __syncthreads();

    float acc[4][4][4];
#pragma unroll
    for (int i = 0; i < 4; i++)
#pragma unroll
        for (int j = 0; j < 4; j++)
#pragma unroll
            for (int q = 0; q < 4; q++) acc[i][j][q] = 0.f;

#pragma unroll
    for (int ks = 0; ks < 8; ks++) {
        uint32_t af[4][4], bf[4][2];
#pragma unroll
        for (int mt = 0; mt < 4; mt++) {
            const uint32_t* pa = Qs + (wm + mt*16 + g)*QST + ks*8 + tg;
            af[mt][0] = pa[0];      af[mt][1] = pa[8*QST];
            af[mt][2] = pa[4];      af[mt][3] = pa[8*QST + 4];
        }
#pragma unroll
        for (int nt = 0; nt < 4; nt++) {
            const uint32_t* pb = Ks + (wn + nt*8 + g)*QST + ks*8 + tg;
            bf[nt][0] = pb[0];      bf[nt][1] = pb[4];
        }
#pragma unroll
        for (int mt = 0; mt < 4; mt++)
#pragma unroll
            for (int nt = 0; nt < 4; nt++)
                mma8(acc[mt][nt], af[mt][0], af[mt][1], af[mt][2], af[mt][3],
                     bf[nt][0], bf[nt][1]);
    }

    float slope = exp2f(-0.5f * (float)(h + 1));
    float s_t[4][2];
#pragma unroll
    for (int mt = 0; mt < 4; mt++) {
#pragma unroll
        for (int rr = 0; rr < 2; rr++) {
            int gi = i0 + wm + mt*16 + g + rr*8;
            size_t rowb = ((size_t)(h*LQ + gi))*LQ;
            float vals[8];
#pragma unroll
            for (int nt = 0; nt < 4; nt++) {
                int j = j0 + wn + nt*8 + 2*tg;
                float2 pv = *(const float2*)&prev[rowb + j];
                int rel0 = gi - j, rel1 = gi - (j + 1);
                float2 ov;
                ov.x = acc[mt][nt][rr*2+0]*0.125f + pv.x +
                       ((rel0 >= 0) ? (-slope*(float)rel0) : -1000000000.0f);
                ov.y = acc[mt][nt][rr*2+1]*0.125f + pv.y +
                       ((rel1 >= 0) ? (-slope*(float)rel1) : -1000000000.0f);
                *(float2*)&dots[rowb + j] = ov;
                vals[nt*2]   = ov.x;
                vals[nt*2+1] = ov.y;
            }
            float ssum = 0.f;
#pragma unroll
            for (int q = 0; q < 8; q++) ssum += __expf(vals[q]);
            s_t[mt][rr] = ssum;
        }
    }

#pragma unroll
    for (int mt = 0; mt < 4; mt++) {
#pragma unroll
        for (int rr = 0; rr < 2; rr++) {
            float s = s_t[mt][rr];
            s += __shfl_xor_sync(0xffffffffu, s, 1);
            s += __shfl_xor_sync(0xffffffffu, s, 2);
            if (tg == 0)
                sparts[(wid & 3)*128 + wm + mt*16 + g + rr*8] = s;
        }
    }
    __syncthreads();
    if (t < 128) {
        float S = sparts[t] + sparts[128 + t] + sparts[256 + t] + sparts[384 + t];
        g_part[((size_t)(h*LQ + i0 + t))*16 + blockIdx.x] = S;
    }
}

// ---------------- row-sum finalize ----------------
__global__ void sumk_kernel() {
    int r = blockIdx.x * 256 + threadIdx.x;   // NH*LQ rows
    const float4* p = (const float4*)&g_part[(size_t)r * 16];
    float4 a = p[0], b = p[1], c = p[2], d = p[3];
    float s = a.x+a.y+a.z+a.w + b.x+b.y+b.z+b.w
            + c.x+c.y+c.z+c.w + d.x+d.y+d.z+d.w;
    g_sinv[r] = 1.f / s;
}

// ---------------- AV fused: probs + attn write + MMA, V via cp.async ----------------
#define PST 72
#define VSTRD 72
#define PS_WORDS (128*PST)        // 9216
#define VS_WORDS (64*VSTRD)       // 4608
#define AV_SMEM_WORDS (PS_WORDS + 2*VS_WORDS)   // 18432 words = 73728 B
__global__ void __launch_bounds__(256, 2)
av_fused(const float* __restrict__ dots, float* __restrict__ attn) {
    extern __shared__ uint32_t sm2[];
    uint32_t* Ps = sm2;                 // [128][72]
    uint32_t* Vs = sm2 + PS_WORDS;      // [2][64][72]
    float* Psf = (float*)Ps;
    int t = threadIdx.x;
    int h = blockIdx.y;
    int i0 = ((int)gridDim.x - 1 - (int)blockIdx.x) * 128;
    int lane = t & 31, wid = t >> 5;
    int g = lane >> 2, tg = lane & 3;
    int wm2 = wid * 16;

    const float* vh = g_v + (size_t)h*LQ*DHD;
    int prow = t >> 1, pc0 = (t & 1) * 32;
    int vrow = t >> 2, vcb = (t & 3) * 16;
    float Si = g_sinv[h*LQ + i0 + prow];
    size_t rowbase = ((size_t)(h*LQ + i0 + prow))*LQ + pc0;

    uint32_t vdst = smem_u32(Vs) + (uint32_t)(vrow*VSTRD + vcb)*4;

    float oacc[8][4];
#pragma unroll
    for (int i = 0; i < 8; i++)
#pragma unroll
        for (int q = 0; q < 4; q++) oacc[i][q] = 0.f;

    int nlive = i0/64 + 2;
    float4 dbuf[8];
    {
        const float* dp = &dots[rowbase];
#pragma unroll
        for (int q = 0; q < 8; q++) dbuf[q] = *(const float4*)(dp + q*4);
        const float* vsrc = vh + (size_t)vrow*DHD + vcb;
#pragma unroll
        for (int q = 0; q < 4; q++)
            CP16(vdst + q*16, vsrc + q*4);
        CP_COMMIT();
    }

    for (int c = 0; c < nlive; c++) {
        int jc = c * 64;
        // prefetch next V chunk
        if (c + 1 < nlive) {
            const float* vsrc = vh + (size_t)(jc + 64 + vrow)*DHD + vcb;
            uint32_t vd = vdst + ((c + 1) & 1) * VS_WORDS * 4;
#pragma unroll
            for (int q = 0; q < 4; q++)
                CP16(vd + q*16, vsrc + q*4);
        }
        CP_COMMIT();

        // probs from dbuf: write attn + stage P (raw f32, STS.128)
#pragma unroll
        for (int q = 0; q < 8; q++) {
            float4 dv = dbuf[q];
            float4 p;
            p.x = __expf(dv.x) * Si;
            p.y = __expf(dv.y) * Si;
            p.z = __expf(dv.z) * Si;
            p.w = __expf(dv.w) * Si;
            *(float4*)&attn[rowbase + jc + q*4] = p;
            *(float4*)&Psf[prow*PST + pc0 + q*4] = p;
        }
        // prefetch next dots into registers
        if (c + 1 < nlive) {
            const float* dp = &dots[rowbase + jc + 64];
#pragma unroll
            for (int q = 0; q < 8; q++) dbuf[q] = *(const float4*)(dp + q*4);
        }
        if (c + 1 < nlive) { CP_WAIT(1); } else { CP_WAIT(0); }
        __syncthreads();

        const uint32_t* Vb = Vs + (c & 1) * VS_WORDS;
#pragma unroll
        for (int ks = 0; ks < 8; ks++) {
            const uint32_t* pa = Ps + (wm2 + g)*PST + ks*8 + tg;
            uint32_t a0 = pa[0], a1 = pa[8*PST], a2 = pa[4], a3 = pa[8*PST + 4];
#pragma unroll
            for (int nt = 0; nt < 8; nt++) {
                const uint32_t* pb = Vb + (ks*8 + tg)*VSTRD + nt*8 + g;
                mma8(oacc[nt], a0, a1, a2, a3, pb[0], pb[4*VSTRD]);
            }
        }
        __syncthreads();
    }

    // masked region: attn = 0
    float4 z = make_float4(0.f, 0.f, 0.f, 0.f);
    for (int jc = nlive*64; jc < LQ; jc += 64) {
#pragma unroll
        for (int q = 0; q < 8; q++)
            *(float4*)&attn[rowbase + jc + q*4] = z;
    }

#pragma unroll
    for (int nt = 0; nt < 8; nt++) {
        int d = nt*8 + 2*tg;
        int i = i0 + wm2 + g;
        *(float2*)&g_o[(size_t)i*DD + h*DHD + d] =
            make_float2(oacc[nt][0], oacc[nt][1]);
        *(float2*)&g_o[(size_t)(i+8)*DD + h*DHD + d] =
            make_float2(oacc[nt][2], oacc[nt][3]);
    }
}

// ---------------- final: y = sigmoid(x@Wg+bg) * (o@Wo+bo) + x ----------------
__global__ void final_kernel(const float* __restrict__ x,
                             const float* __restrict__ bo,
                             const float* __restrict__ bg,
                             float* __restrict__ y) {
    int idx = blockIdx.x * 256 + threadIdx.x;
    int n = idx & (DD - 1);
    float yo = g_yo[idx] + bo[n];
    float gg = g_gg[idx] + bg[n];
    float gate = 1.f / (1.f + __expf(-gg));
    y[idx] = gate * yo + x[idx];
}

extern "C" void kernel_launch(void* const* d_in, const int* in_sizes, int n_in,
                              void* d_out, int out_size) {
    const float* x     = (const float*)d_in[0];
    const float* prev  = (const float*)d_in[1];
    const float* Wq    = (const float*)d_in[2];
    const float* Wk    = (const float*)d_in[3];
    const float* Wv    = (const float*)d_in[4];
    const float* Wo    = (const float*)d_in[5];
    const float* bo    = (const float*)d_in[6];
    const float* gamma = (const float*)d_in[7];
    const float* beta  = (const float*)d_in[8];
    const float* Wg    = (const float*)d_in[9];
    const float* bg    = (const float*)d_in[10];

    float* y    = (float*)d_out;
    float* attn = y + (size_t)LQ * DD;
    float* dots = attn + (size_t)NH * LQ * LQ;

    float *ph, *pq, *pk, *pv, *po, *pyo, *pgg;
    cudaGetSymbolAddress((void**)&ph,  g_h);
    cudaGetSymbolAddress((void**)&pq,  g_q);
    cudaGetSymbolAddress((void**)&pk,  g_k);
    cudaGetSymbolAddress((void**)&pv,  g_v);
    cudaGetSymbolAddress((void**)&po,  g_o);
    cudaGetSymbolAddress((void**)&pyo, g_yo);
    cudaGetSymbolAddress((void**)&pgg, g_gg);

    size_t gsmb = (size_t)GEMM_SMEM_WORDS * 4;
    cudaFuncSetAttribute(gemm_qkv, cudaFuncAttributeMaxDynamicSharedMemorySize, (int)gsmb);
    cudaFuncSetAttribute(gemm_ow,  cudaFuncAttributeMaxDynamicSharedMemorySize, (int)gsmb);
    size_t qsmb = (size_t)QK_SMEM_WORDS * 4;
    cudaFuncSetAttribute(qk_tf32, cudaFuncAttributeMaxDynamicSharedMemorySize, (int)qsmb);
    size_t avsmb = (size_t)AV_SMEM_WORDS * 4;
    cudaFuncSetAttribute(av_fused, cudaFuncAttributeMaxDynamicSharedMemorySize, (int)avsmb);

    ln_kernel<<<LQ, 256>>>(x, gamma, beta);

    gemm_qkv<<<dim3(8, 16, 3), 256, gsmb>>>(ph, Wq, Wk, Wv, pq, pk, pv);

    rope_kernel<<<(NH*LQ*8)/256, 256>>>();

    qk_tf32<<<dim3(16, 16, 16), 256, qsmb>>>(prev, dots);
    sumk_kernel<<<(NH*LQ)/256, 256>>>();
    av_fused<<<dim3(16, 16), 256, avsmb>>>(dots, attn);

    gemm_ow<<<dim3(8, 16, 2), 256, gsmb>>>(po, Wo, pyo, x, Wg, pgg);

    final_kernel<<<(LQ*DD)/256, 256>>>(x, bo, bg, y);
}